// round 1
// baseline (speedup 1.0000x reference)
#include <cuda_runtime.h>

#define BB 4
#define SS 8192
#define DD 512
#define KK 20
#define CHUNKS 64       // chunks per batch, 128 tokens each
#define TPB1 128

// ---- scratch (device globals: allocation-free) ----
__device__ float g_attn[BB*SS*KK];              // 2.6 MB
__device__ float g_ypart[BB*CHUNKS*KK*DD];      // 10.5 MB
__device__ float g_y[BB*KK*DD];
__device__ float g_tmp[BB*KK*DD];
__device__ float g_z[BB*KK*DD];

// =====================================================================
// Kernel 1: per-token RBF attn + per-chunk partial y = attn^T @ x
// grid(CHUNKS, B), 128 threads. Thread t owns token s0+t (phase A/B)
// and d-quad [4*t, 4*t+4) (phase C).
// =====================================================================
__global__ __launch_bounds__(TPB1)
void k1_attn_y(const float* __restrict__ x, const float* __restrict__ pos,
               const float* __restrict__ lsc, const float* __restrict__ amp)
{
    extern __shared__ float sm[];
    float4* pos4   = (float4*)sm;                 // [20][128] f4  (40960 B)
    float4* xs4    = pos4 + KK*128;               // [128][17] f4  (34816 B)
    float*  attn_s = (float*)(xs4 + 128*17);      // [128][20]     (10240 B)
    float*  coef   = attn_s + 128*KK;             // [20]
    float*  amps   = coef + KK;                   // [20]
    float*  c2s    = amps + KK;                   // [20]

    const int b     = blockIdx.y;
    const int chunk = blockIdx.x;
    const int s0    = chunk * 128;
    const int tid   = threadIdx.x;

    // stage positions (uniform-read later -> no padding needed)
    const float4* pg = (const float4*)pos;
    for (int i = tid; i < KK*128; i += TPB1) pos4[i] = pg[i];
    __syncthreads();
    if (tid < KK) {
        float s = expf(lsc[tid]);
        coef[tid] = -0.5f / (s*s);
        amps[tid] = amp[tid];
        const float4* pr = pos4 + tid*128;
        float c2 = 0.f;
        for (int j = 0; j < 128; ++j) {
            float4 p = pr[j];
            c2 += p.x*p.x + p.y*p.y + p.z*p.z + p.w*p.w;
        }
        c2s[tid] = c2;
    }

    // ---- phase A: xc[k] = <x_s, pos_k>, x2 = <x_s, x_s> (thread-per-token)
    float xc[KK];
    #pragma unroll
    for (int k = 0; k < KK; ++k) xc[k] = 0.f;
    float x2 = 0.f;

    const float4* xg = (const float4*)(x + ((size_t)b*SS + s0)*DD);
    for (int dc = 0; dc < 8; ++dc) {            // 8 chunks of 64 d
        __syncthreads();
        for (int i = tid; i < 128*16; i += TPB1) {
            int r = i >> 4, c = i & 15;
            xs4[r*17 + c] = xg[(size_t)r*128 + dc*16 + c];
        }
        __syncthreads();
        const float4* xr = xs4 + tid*17;        // odd f4 stride -> optimal LDS.128
        for (int j = 0; j < 16; ++j) {
            float4 xv = xr[j];
            x2 += xv.x*xv.x + xv.y*xv.y + xv.z*xv.z + xv.w*xv.w;
            const float4* pc = pos4 + (dc*16 + j);
            #pragma unroll
            for (int k = 0; k < KK; ++k) {
                float4 pv = pc[k*128];          // uniform across warp (broadcast)
                xc[k] += xv.x*pv.x + xv.y*pv.y + xv.z*pv.z + xv.w*pv.w;
            }
        }
    }

    // ---- phase B: gauss -> normalized attn
    float g[KK]; float gsum = 0.f;
    #pragma unroll
    for (int k = 0; k < KK; ++k) {
        float d2 = fmaxf(x2 - 2.f*xc[k] + c2s[k], 0.f);
        float gg = amps[k] * expf(coef[k] * d2);
        g[k] = gg; gsum += gg;
    }
    float inv = 1.0f / (gsum + 1e-8f);
    #pragma unroll
    for (int k = 0; k < KK; ++k) attn_s[tid*KK + k] = g[k] * inv;

    // store attn to global (5x STG.128 per token; 80B-aligned base)
    {
        float4* ag   = (float4*)(g_attn + ((size_t)(b*SS + s0 + tid))*KK);
        float4* asrc = (float4*)(attn_s + tid*KK);
        #pragma unroll
        for (int q = 0; q < 5; ++q) ag[q] = asrc[q];
    }
    __syncthreads();

    // ---- phase C: y_partial[k][d-quad] += attn[t][k] * x[t][d-quad]
    float4 acc[KK];
    #pragma unroll
    for (int k = 0; k < KK; ++k) acc[k] = make_float4(0.f,0.f,0.f,0.f);

    const float4* xcol = (const float4*)(x + ((size_t)b*SS + s0)*DD) + tid;
    float4 xv = xcol[0];                        // coalesced, L2-hot (just read in A)
    for (int t = 0; t < 128; ++t) {
        int tn = (t < 127) ? t + 1 : 127;
        float4 xn = xcol[(size_t)tn*128];       // prefetch for MLP
        const float* at = attn_s + t*KK;        // uniform broadcast reads
        #pragma unroll
        for (int k = 0; k < KK; ++k) {
            float a = at[k];
            acc[k].x += a*xv.x; acc[k].y += a*xv.y;
            acc[k].z += a*xv.z; acc[k].w += a*xv.w;
        }
        xv = xn;
    }
    float4* yp = (float4*)(g_ypart + ((size_t)(b*CHUNKS + chunk))*KK*DD) + tid;
    #pragma unroll
    for (int k = 0; k < KK; ++k) yp[k*128] = acc[k];
}

// =====================================================================
// Kernel 2: reduce partials -> y[b][k][d]  (deterministic, no atomics)
// =====================================================================
__global__ void k2_reduce()
{
    int idx = blockIdx.x*blockDim.x + threadIdx.x;
    if (idx >= BB*KK*DD) return;
    int b = idx / (KK*DD);
    int rem = idx - b*(KK*DD);
    const float* p = g_ypart + (size_t)b*CHUNKS*KK*DD + rem;
    float s = 0.f;
    #pragma unroll 8
    for (int c = 0; c < CHUNKS; ++c) s += p[(size_t)c*KK*DD];
    g_y[idx] = s;
}

// =====================================================================
// Tiny projections: out[b][k][e] = sum_d in[b][k][d] * W[e][d]
// grid(8, B): CTA covers 64 e-columns, all 20 k, one batch.
// =====================================================================
__device__ __forceinline__
void proj_body(const float* __restrict__ in, const float* __restrict__ W,
               float* __restrict__ out)
{
    __shared__ float4 ys4[KK*128];              // 40 KB (static, <48KB)
    int b  = blockIdx.y;
    int e0 = blockIdx.x * 64;
    const float4* ig = (const float4*)(in + (size_t)b*KK*DD);
    for (int i = threadIdx.x; i < KK*128; i += 256) ys4[i] = ig[i];
    __syncthreads();

    int e  = e0 + (threadIdx.x >> 2);
    int kq = threadIdx.x & 3;                   // k = kq*5 + i
    float acc[5] = {0.f,0.f,0.f,0.f,0.f};
    const float4* wr = (const float4*)(W + (size_t)e*DD);
    for (int j = 0; j < 128; ++j) {
        float4 wv = wr[j];
        #pragma unroll
        for (int i = 0; i < 5; ++i) {
            float4 yv = ys4[(kq*5 + i)*128 + j];
            acc[i] += yv.x*wv.x + yv.y*wv.y + yv.z*wv.z + yv.w*wv.w;
        }
    }
    #pragma unroll
    for (int i = 0; i < 5; ++i)
        out[((size_t)b*KK + kq*5 + i)*DD + e] = acc[i];
}

__global__ __launch_bounds__(256) void k3_proj_v(const float* __restrict__ W)
{ proj_body(g_y, W, g_tmp); }
__global__ __launch_bounds__(256) void k4_proj_o(const float* __restrict__ W)
{ proj_body(g_tmp, W, g_z); }

// =====================================================================
// Kernel 5: out[b][s][:] = sum_k attn[b][s][k] * z[b][k][:]
// grid(CHUNKS, B), 256 threads. z staged in SMEM; 4-token register
// blocking amortizes LDS.128 crossbar traffic.
// =====================================================================
__global__ __launch_bounds__(256)
void k5_scatter(float* __restrict__ out)
{
    extern __shared__ float sm[];
    float4* z4     = (float4*)sm;               // [20][128] f4 (40 KB)
    float*  attn_s = (float*)(z4 + KK*128);     // [128][20]   (10 KB)

    int b = blockIdx.y, chunk = blockIdx.x, s0 = chunk*128, tid = threadIdx.x;

    const float4* zg = (const float4*)(g_z + (size_t)b*KK*DD);
    for (int i = tid; i < KK*128; i += 256) z4[i] = zg[i];
    const float* ag = g_attn + ((size_t)b*SS + s0)*KK;
    for (int i = tid; i < 128*KK; i += 256) attn_s[i] = ag[i];
    __syncthreads();

    int dq = tid & 127;                         // d-quad index
    int tg = tid >> 7;                          // token half (0/1)

    for (int tb = 0; tb < 64; tb += 4) {
        int t = tg*64 + tb;
        float4 a0 = make_float4(0,0,0,0), a1 = a0, a2 = a0, a3 = a0;
        const float* at = attn_s + t*KK;        // uniform broadcast
        #pragma unroll
        for (int k = 0; k < KK; ++k) {
            float4 zv = z4[k*128 + dq];         // conflict-free LDS.128
            float w0 = at[k], w1 = at[KK+k], w2 = at[2*KK+k], w3 = at[3*KK+k];
            a0.x += w0*zv.x; a0.y += w0*zv.y; a0.z += w0*zv.z; a0.w += w0*zv.w;
            a1.x += w1*zv.x; a1.y += w1*zv.y; a1.z += w1*zv.z; a1.w += w1*zv.w;
            a2.x += w2*zv.x; a2.y += w2*zv.y; a2.z += w2*zv.z; a2.w += w2*zv.w;
            a3.x += w3*zv.x; a3.y += w3*zv.y; a3.z += w3*zv.z; a3.w += w3*zv.w;
        }
        float4* og = (float4*)(out + ((size_t)b*SS + s0 + t)*DD) + dq;
        og[0]   = a0;
        og[128] = a1;
        og[256] = a2;
        og[384] = a3;
    }
}

// =====================================================================
extern "C" void kernel_launch(void* const* d_in, const int* in_sizes, int n_in,
                              void* d_out, int out_size)
{
    const float* x   = (const float*)d_in[0];
    const float* pos = (const float*)d_in[1];
    const float* lsc = (const float*)d_in[2];
    const float* amp = (const float*)d_in[3];
    const float* wv  = (const float*)d_in[4];
    const float* wo  = (const float*)d_in[5];
    float* out = (float*)d_out;

    const int sm1 = (KK*128 + 128*17)*16 + (128*KK + 3*KK)*4;   // 86256 B
    const int sm5 = KK*128*16 + 128*KK*4;                       // 51200 B
    cudaFuncSetAttribute(k1_attn_y,  cudaFuncAttributeMaxDynamicSharedMemorySize, sm1);
    cudaFuncSetAttribute(k5_scatter, cudaFuncAttributeMaxDynamicSharedMemorySize, sm5);

    dim3 g1(CHUNKS, BB);
    k1_attn_y<<<g1, TPB1, sm1>>>(x, pos, lsc, amp);
    k2_reduce<<<(BB*KK*DD + 255)/256, 256>>>();
    dim3 gp(8, BB);
    k3_proj_v<<<gp, 256>>>(wv);
    k4_proj_o<<<gp, 256>>>(wo);
    dim3 g5(CHUNKS, BB);
    k5_scatter<<<g5, 256, sm5>>>(out);
}

// round 2
// speedup vs baseline: 1.3211x; 1.3211x over previous
#include <cuda_runtime.h>

#define BB 4
#define SS 8192
#define DD 512
#define KK 20
#define TOK 256          // tokens per chunk (k1/k5)
#define NCH 32           // chunks per batch
#define TPB 256

// ---- scratch (device globals: allocation-free) ----
__device__ double g_attn2[BB*SS*KK];            // dup-packed (a,a)  5.2 MB
__device__ double g_ypart[BB*NCH*KK*(DD/2)];    // packed f32x2 pairs 5.2 MB
__device__ float  g_y[BB*KK*DD];
__device__ float  g_tmp[BB*KK*DD];
__device__ float  g_z[BB*KK*DD];

// ---- f32x2 helpers ----
__device__ __forceinline__ void ffma2(double& acc, double a, double b) {
    asm("fma.rn.f32x2 %0, %1, %2, %0;" : "+d"(acc) : "d"(a), "d"(b));
}
__device__ __forceinline__ float2 dsplit(double v) {
    float2 f;
    asm("mov.b64 {%0, %1}, %2;" : "=f"(f.x), "=f"(f.y) : "d"(v));
    return f;
}
__device__ __forceinline__ double ddup(float a) {
    double d;
    asm("mov.b64 %0, {%1, %1};" : "=d"(d) : "f"(a));
    return d;
}

// =====================================================================
// Kernel 1: RBF attn (per token) + per-chunk partial y = attn^T @ x
// grid(NCH, B), 256 threads. Thread t = token (phases A/B), d-pair (C).
// =====================================================================
__global__ __launch_bounds__(TPB)
void k1_attn_y(const float* __restrict__ x, const float* __restrict__ pos,
               const float* __restrict__ lsc, const float* __restrict__ amp)
{
    extern __shared__ char smraw[];
    double2* pos2  = (double2*)smraw;                    // [20][128]  40960 B
    double2* xs2   = pos2 + KK*128;                      // [256][17]  69632 B
    double*  attn2 = (double*)(xs2 + TOK*17);            // [256][20]  40960 B
    float*   coef  = (float*)(attn2 + TOK*KK);
    float*   amps  = coef + KK;
    float*   c2s   = amps + KK;

    const int b   = blockIdx.y;
    const int s0  = blockIdx.x * TOK;
    const int tid = threadIdx.x;

    // stage positions (packed pairs; bitwise copy of float4)
    const double2* pg = (const double2*)pos;
    for (int i = tid; i < KK*128; i += TPB) pos2[i] = pg[i];
    __syncthreads();
    if (tid < KK) {
        float s = expf(lsc[tid]);
        coef[tid] = -0.5f/(s*s);
        amps[tid] = amp[tid];
        float c2 = 0.f;
        const double2* pr = pos2 + tid*128;
        for (int j = 0; j < 128; ++j) {
            double2 p = pr[j];
            float2 a = dsplit(p.x), q = dsplit(p.y);
            c2 += a.x*a.x + a.y*a.y + q.x*q.x + q.y*q.y;
        }
        c2s[tid] = c2;
    }

    // ---- phase A: xc[k] = <x_s, pos_k>, x2 = <x_s,x_s>  (thread-per-token)
    double acc2[KK];
    #pragma unroll
    for (int k = 0; k < KK; ++k) acc2[k] = 0.0;
    double x2a = 0.0;

    const float4* xg = (const float4*)(x + ((size_t)b*SS + s0)*DD);
    for (int dc = 0; dc < 8; ++dc) {            // 8 chunks of 64 d (16 f4)
        __syncthreads();
        for (int i = tid; i < TOK*16; i += TPB) {
            int r = i >> 4, c = i & 15;
            ((float4*)xs2)[r*17 + c] = xg[(size_t)r*128 + dc*16 + c];
        }
        __syncthreads();
        const double2* xr = xs2 + tid*17;
        #pragma unroll 4
        for (int c = 0; c < 16; ++c) {
            double2 xv = xr[c];
            ffma2(x2a, xv.x, xv.x);
            ffma2(x2a, xv.y, xv.y);
            const double2* pc = pos2 + (dc*16 + c);
            #pragma unroll
            for (int k = 0; k < KK; ++k) {
                double2 pv = pc[k*128];          // uniform broadcast LDS.128
                ffma2(acc2[k], xv.x, pv.x);
                ffma2(acc2[k], xv.y, pv.y);
            }
        }
    }

    // ---- phase B: gauss -> normalized attn, store dup-packed
    float2 xs_ = dsplit(x2a);
    float x2 = xs_.x + xs_.y;
    float g[KK]; float gsum = 0.f;
    #pragma unroll
    for (int k = 0; k < KK; ++k) {
        float2 f = dsplit(acc2[k]);
        float xc = f.x + f.y;
        float d2 = fmaxf(x2 - 2.f*xc + c2s[k], 0.f);
        float gg = amps[k] * expf(coef[k]*d2);
        g[k] = gg; gsum += gg;
    }
    float inv = 1.0f/(gsum + 1e-8f);
    {
        double2 packed[10];
        #pragma unroll
        for (int q = 0; q < 10; ++q) {
            packed[q].x = ddup(g[2*q]*inv);
            packed[q].y = ddup(g[2*q+1]*inv);
        }
        double2* as = (double2*)(attn2 + tid*KK);
        double2* ag = (double2*)(g_attn2 + ((size_t)(b*SS + s0 + tid))*KK);
        #pragma unroll
        for (int q = 0; q < 10; ++q) { as[q] = packed[q]; ag[q] = packed[q]; }
    }
    __syncthreads();

    // ---- phase C: ypart[k][dpair] += attn[t][k] * x[t][dpair]
    #pragma unroll
    for (int k = 0; k < KK; ++k) acc2[k] = 0.0;
    const double* xcol = (const double*)x + ((size_t)b*SS + s0)*(DD/2) + tid;
    #pragma unroll 4
    for (int t = 0; t < TOK; ++t) {
        double xd = xcol[(size_t)t*(DD/2)];      // coalesced, L2-hot
        const double2* arow = (const double2*)(attn2 + t*KK);
        #pragma unroll
        for (int q = 0; q < 10; ++q) {
            double2 a2 = arow[q];                // broadcast LDS.128
            ffma2(acc2[2*q],   a2.x, xd);
            ffma2(acc2[2*q+1], a2.y, xd);
        }
    }
    double* yp = g_ypart + ((size_t)(b*NCH + blockIdx.x))*KK*(DD/2) + tid;
    #pragma unroll
    for (int k = 0; k < KK; ++k) yp[k*(DD/2)] = acc2[k];
}

// =====================================================================
// Kernel 2: reduce chunk partials -> y[b][k][d] (float view of packed)
// =====================================================================
__global__ void k2_reduce()
{
    int idx = blockIdx.x*blockDim.x + threadIdx.x;     // over B*K*D floats
    if (idx >= BB*KK*DD) return;
    int b = idx / (KK*DD);
    int rem = idx - b*(KK*DD);
    const float* p = (const float*)g_ypart + (size_t)b*NCH*KK*DD + rem;
    float s = 0.f;
    #pragma unroll 8
    for (int c = 0; c < NCH; ++c) s += p[(size_t)c*KK*DD];
    g_y[idx] = s;
}

// =====================================================================
// Tiny projections: out[b][k][e] = sum_d in[b][k][d]*W[e][d]
// grid(32, B) = 128 CTAs, 320 threads: thread = (k, e_local) pair.
// =====================================================================
__device__ __forceinline__
void proj_body(const float* __restrict__ in, const float* __restrict__ W,
               float* __restrict__ out)
{
    __shared__ float ys[KK*DD];                  // 40 KB
    const int b  = blockIdx.y;
    const int e0 = blockIdx.x * 16;
    const float4* ig = (const float4*)(in + (size_t)b*KK*DD);
    for (int i = threadIdx.x; i < KK*DD/4; i += 320) ((float4*)ys)[i] = ig[i];
    __syncthreads();

    const int k  = threadIdx.x >> 4;             // 0..19
    const int e  = e0 + (threadIdx.x & 15);
    const double2* wr = (const double2*)(W + (size_t)e*DD);
    const double2* yr = (const double2*)ys + k*128;
    double accA = 0.0, accB = 0.0, accC = 0.0, accD = 0.0;
    #pragma unroll 8
    for (int j = 0; j < 128; j += 2) {
        double2 w0 = wr[j],   y0 = yr[j];
        double2 w1 = wr[j+1], y1 = yr[j+1];
        ffma2(accA, w0.x, y0.x);
        ffma2(accB, w0.y, y0.y);
        ffma2(accC, w1.x, y1.x);
        ffma2(accD, w1.y, y1.y);
    }
    float2 fa = dsplit(accA), fb = dsplit(accB), fc = dsplit(accC), fd = dsplit(accD);
    out[((size_t)b*KK + k)*DD + e] = (fa.x+fa.y) + (fb.x+fb.y) + (fc.x+fc.y) + (fd.x+fd.y);
}

__global__ __launch_bounds__(320) void k3_proj_v(const float* __restrict__ W)
{ proj_body(g_y, W, g_tmp); }
__global__ __launch_bounds__(320) void k4_proj_o(const float* __restrict__ W)
{ proj_body(g_tmp, W, g_z); }

// =====================================================================
// Kernel 5: out[b][s][:] = sum_k attn[b][s][k] * z[b][k][:]
// grid(NCH, B), 256 threads. z in registers (per d-pair), attn broadcast.
// =====================================================================
__global__ __launch_bounds__(TPB)
void k5_scatter(float* __restrict__ out)
{
    extern __shared__ char smraw[];
    double*  zd  = (double*)smraw;               // [20][256] packed pairs 40 KB
    double2* as2 = (double2*)(zd + KK*(DD/2));   // [256][10]              40 KB

    const int b   = blockIdx.y;
    const int s0  = blockIdx.x * TOK;
    const int tid = threadIdx.x;

    const double2* zg = (const double2*)(g_z + (size_t)b*KK*DD);
    for (int i = tid; i < KK*DD/4; i += TPB) ((double2*)zd)[i] = zg[i];
    const double2* ag = (const double2*)(g_attn2 + ((size_t)b*SS + s0)*KK);
    for (int i = tid; i < TOK*10; i += TPB) as2[i] = ag[i];
    __syncthreads();

    double zr[KK];
    #pragma unroll
    for (int k = 0; k < KK; ++k) zr[k] = zd[k*(DD/2) + tid];

    double* og = (double*)out + ((size_t)b*SS + s0)*(DD/2) + tid;
    #pragma unroll 2
    for (int t = 0; t < TOK; ++t) {
        const double2* arow = as2 + t*10;
        double acc = 0.0;
        #pragma unroll
        for (int q = 0; q < 10; ++q) {
            double2 a2 = arow[q];                // broadcast LDS.128
            ffma2(acc, a2.x, zr[2*q]);
            ffma2(acc, a2.y, zr[2*q+1]);
        }
        og[(size_t)t*(DD/2)] = acc;              // packed (even,odd) floats
    }
}

// =====================================================================
extern "C" void kernel_launch(void* const* d_in, const int* in_sizes, int n_in,
                              void* d_out, int out_size)
{
    const float* x   = (const float*)d_in[0];
    const float* pos = (const float*)d_in[1];
    const float* lsc = (const float*)d_in[2];
    const float* amp = (const float*)d_in[3];
    const float* wv  = (const float*)d_in[4];
    const float* wo  = (const float*)d_in[5];
    float* out = (float*)d_out;

    const int sm1 = KK*128*16 + TOK*17*16 + TOK*KK*8 + 3*KK*4;  // ~151.6 KB
    const int sm5 = KK*(DD/2)*8 + TOK*10*16;                    // 80 KB
    static int attr_done = 0;
    cudaFuncSetAttribute(k1_attn_y,  cudaFuncAttributeMaxDynamicSharedMemorySize, sm1);
    cudaFuncSetAttribute(k5_scatter, cudaFuncAttributeMaxDynamicSharedMemorySize, sm5);
    (void)attr_done;

    dim3 g1(NCH, BB);
    k1_attn_y<<<g1, TPB, sm1>>>(x, pos, lsc, amp);
    k2_reduce<<<(BB*KK*DD + 255)/256, 256>>>();
    dim3 gp(32, BB);
    k3_proj_v<<<gp, 320>>>(wv);
    k4_proj_o<<<gp, 320>>>(wo);
    dim3 g5(NCH, BB);
    k5_scatter<<<g5, TPB, sm5>>>(out);
}

// round 3
// speedup vs baseline: 1.8711x; 1.4162x over previous
#include <cuda_runtime.h>

#define BB 4
#define SS 8192
#define DD 512
#define KK 20

// ---- scratch (device globals: allocation-free) ----
__device__ double g_attn2[BB*SS*KK];              // dup-packed (a,a)  5.2 MB
__device__ double g_ypart[BB*64*KK*(DD/2)];       // packed pairs     10.5 MB
__device__ float  g_y[BB*KK*DD];
__device__ float  g_tmp[BB*KK*DD];
__device__ float  g_z[BB*KK*DD];
__device__ float  g_cst[64];                      // [0..19] coef, [20..39] amp, [40..59] c2

// ---- f32x2 helpers ----
__device__ __forceinline__ void ffma2(double& acc, double a, double b) {
    asm("fma.rn.f32x2 %0, %1, %2, %0;" : "+d"(acc) : "d"(a), "d"(b));
}
__device__ __forceinline__ float2 dsplit(double v) {
    float2 f;
    asm("mov.b64 {%0, %1}, %2;" : "=f"(f.x), "=f"(f.y) : "d"(v));
    return f;
}
__device__ __forceinline__ double ddup(float a) {
    double d;
    asm("mov.b64 %0, {%1, %1};" : "=d"(d) : "f"(a));
    return d;
}

// =====================================================================
// k0: per-splat constants (coef, amp, c2).  1 block, 20 warps.
// =====================================================================
__global__ __launch_bounds__(640)
void k0_setup(const float* __restrict__ pos, const float* __restrict__ lsc,
              const float* __restrict__ amp)
{
    int w = threadIdx.x >> 5, l = threadIdx.x & 31;
    if (w >= KK) return;
    const float4* pr = (const float4*)(pos + (size_t)w*DD) + l*4;
    float s = 0.f;
    #pragma unroll
    for (int j = 0; j < 4; ++j) {
        float4 p = pr[j];
        s += p.x*p.x + p.y*p.y + p.z*p.z + p.w*p.w;
    }
    #pragma unroll
    for (int off = 16; off; off >>= 1) s += __shfl_xor_sync(0xffffffffu, s, off);
    if (l == 0) {
        float sc = expf(lsc[w]);
        g_cst[w]      = -0.5f/(sc*sc);
        g_cst[20 + w] = amp[w];
        g_cst[40 + w] = s;
    }
}

// =====================================================================
// k1a: RBF attention weights.  grid(64,B), 128 thr, thread = token.
// x staged in smem in 16 rounds of 32 floats/token, register prefetch.
// =====================================================================
__global__ __launch_bounds__(128)
void k1a_attn(const float* __restrict__ x, const float* __restrict__ pos)
{
    extern __shared__ char smraw[];
    double2* pos2 = (double2*)smraw;                 // [20][128]  40960 B
    float4*  xs   = (float4*)(pos2 + KK*128);        // [128][9]   18432 B
    float*   cst  = (float*)(xs + 128*9);            // 64 floats

    const int b = blockIdx.y, s0 = blockIdx.x*128, tid = threadIdx.x;

    const double2* pg = (const double2*)pos;
    for (int i = tid; i < KK*128; i += 128) pos2[i] = pg[i];
    if (tid < 60) cst[tid] = g_cst[tid];

    const float4* xg = (const float4*)(x + ((size_t)b*SS + s0)*DD);

    float4 pf[8];
    #pragma unroll
    for (int j = 0; j < 8; ++j) {
        int i = tid + j*128;
        pf[j] = xg[(size_t)(i>>3)*128 + (i&7)];
    }

    double acc2[KK];
    #pragma unroll
    for (int k = 0; k < KK; ++k) acc2[k] = 0.0;
    double x2a = 0.0;

    for (int dc = 0; dc < 16; ++dc) {
        __syncthreads();
        #pragma unroll
        for (int j = 0; j < 8; ++j) {
            int i = tid + j*128;
            xs[(i>>3)*9 + (i&7)] = pf[j];
        }
        __syncthreads();
        if (dc < 15) {
            #pragma unroll
            for (int j = 0; j < 8; ++j) {
                int i = tid + j*128;
                pf[j] = xg[(size_t)(i>>3)*128 + (dc+1)*8 + (i&7)];
            }
        }
        const double2* xr = (const double2*)xs + tid*9;
        #pragma unroll
        for (int c = 0; c < 8; ++c) {
            double2 xv = xr[c];
            ffma2(x2a, xv.x, xv.x);
            ffma2(x2a, xv.y, xv.y);
            const double2* pc = pos2 + dc*8 + c;
            #pragma unroll
            for (int k = 0; k < KK; ++k) {
                double2 pv = pc[k*128];              // uniform broadcast LDS.128
                ffma2(acc2[k], xv.x, pv.x);
                ffma2(acc2[k], xv.y, pv.y);
            }
        }
    }

    float2 xf = dsplit(x2a);
    float x2 = xf.x + xf.y;
    float g[KK]; float gsum = 0.f;
    #pragma unroll
    for (int k = 0; k < KK; ++k) {
        float2 f = dsplit(acc2[k]);
        float xc = f.x + f.y;
        float d2 = fmaxf(x2 - 2.f*xc + cst[40+k], 0.f);
        float gg = cst[20+k] * expf(cst[k]*d2);
        g[k] = gg; gsum += gg;
    }
    float inv = 1.0f/(gsum + 1e-8f);
    double2* ag = (double2*)(g_attn2 + (size_t)(b*SS + s0 + tid)*KK);
    #pragma unroll
    for (int q = 0; q < 10; ++q) {
        double2 pk; pk.x = ddup(g[2*q]*inv); pk.y = ddup(g[2*q+1]*inv);
        ag[q] = pk;
    }
}

// =====================================================================
// k1b: partial y[k][d] = sum_t attn[t][k] x[t][d].  grid(64,B), 256 thr.
// thread = d-pair; explicit 4-deep x prefetch.
// =====================================================================
__global__ __launch_bounds__(256)
void k1b_ypart(const float* __restrict__ x)
{
    __shared__ double attn_s[128*KK];                // 20480 B
    const int b = blockIdx.y, ch = blockIdx.x, s0 = ch*128, tid = threadIdx.x;

    const double2* ag = (const double2*)(g_attn2 + (size_t)(b*SS + s0)*KK);
    for (int i = tid; i < 128*KK/2; i += 256) ((double2*)attn_s)[i] = ag[i];
    __syncthreads();

    double acc2[KK];
    #pragma unroll
    for (int k = 0; k < KK; ++k) acc2[k] = 0.0;

    const double* xcol = (const double*)x + (size_t)(b*SS + s0)*(DD/2) + tid;
    double xd[4];
    #pragma unroll
    for (int j = 0; j < 4; ++j) xd[j] = xcol[(size_t)j*(DD/2)];

    for (int t = 0; t < 128; t += 4) {
        double xn[4];
        if (t + 4 < 128) {
            #pragma unroll
            for (int j = 0; j < 4; ++j) xn[j] = xcol[(size_t)(t+4+j)*(DD/2)];
        }
        #pragma unroll
        for (int u = 0; u < 4; ++u) {
            const double2* ar = (const double2*)(attn_s + (t+u)*KK);
            #pragma unroll
            for (int q = 0; q < 10; ++q) {
                double2 a2 = ar[q];                  // broadcast LDS.128
                ffma2(acc2[2*q],   a2.x, xd[u]);
                ffma2(acc2[2*q+1], a2.y, xd[u]);
            }
        }
        #pragma unroll
        for (int j = 0; j < 4; ++j) xd[j] = xn[j];
    }
    double* yp = g_ypart + (size_t)((b*64 + ch)*KK)*(DD/2) + tid;
    #pragma unroll
    for (int k = 0; k < KK; ++k) yp[k*(DD/2)] = acc2[k];
}

// =====================================================================
// k2: reduce 64 chunk partials -> y
// =====================================================================
__global__ void k2_reduce()
{
    int idx = blockIdx.x*256 + threadIdx.x;
    if (idx >= BB*KK*DD) return;
    int b = idx / (KK*DD);
    int rem = idx - b*(KK*DD);
    const float* p = (const float*)g_ypart + (size_t)b*64*KK*DD + rem;
    float s = 0.f;
    #pragma unroll 8
    for (int c = 0; c < 64; ++c) s += p[(size_t)c*KK*DD];
    g_y[idx] = s;
}

// =====================================================================
// Projections: warp per (e,b) output row; W in regs, y via LDG (L2-hot),
// butterfly shuffle reduction.  grid(64,B), 256 thr.
// =====================================================================
__device__ __forceinline__
void proj_body(const float* __restrict__ in, const float* __restrict__ W,
               float* __restrict__ out)
{
    const int b = blockIdx.y;
    const int e = blockIdx.x*8 + (threadIdx.x >> 5);
    const int l = threadIdx.x & 31;

    const double2* wr = (const double2*)(W + (size_t)e*DD) + l*4;
    double2 w0 = wr[0], w1 = wr[1], w2 = wr[2], w3 = wr[3];

    const double2* yb = (const double2*)(in + (size_t)b*KK*DD) + l*4;
    float res = 0.f;
    #pragma unroll
    for (int k = 0; k < KK; ++k) {
        const double2* yr = yb + k*128;
        double2 y0 = yr[0], y1 = yr[1], y2 = yr[2], y3 = yr[3];
        double accA = 0.0, accB = 0.0;
        ffma2(accA, w0.x, y0.x); ffma2(accB, w0.y, y0.y);
        ffma2(accA, w1.x, y1.x); ffma2(accB, w1.y, y1.y);
        ffma2(accA, w2.x, y2.x); ffma2(accB, w2.y, y2.y);
        ffma2(accA, w3.x, y3.x); ffma2(accB, w3.y, y3.y);
        float2 fa = dsplit(accA), fb = dsplit(accB);
        float s = (fa.x + fa.y) + (fb.x + fb.y);
        #pragma unroll
        for (int off = 16; off; off >>= 1) s += __shfl_xor_sync(0xffffffffu, s, off);
        if (l == k) res = s;
    }
    if (l < KK) out[((size_t)b*KK + l)*DD + e] = res;
}

__global__ __launch_bounds__(256) void k3_proj_v(const float* __restrict__ W)
{ proj_body(g_y, W, g_tmp); }
__global__ __launch_bounds__(256) void k4_proj_o(const float* __restrict__ W)
{ proj_body(g_tmp, W, g_z); }

// =====================================================================
// k5: out[s][:] = sum_k attn[s][k] z[k][:].  grid(64,B), 128 thr.
// thread = float4 column; z in regs; attn broadcast from smem.
// =====================================================================
__global__ __launch_bounds__(128)
void k5_scatter(float* __restrict__ out)
{
    __shared__ double attn_s[128*KK];                // 20480 B
    const int b = blockIdx.y, s0 = blockIdx.x*128, tid = threadIdx.x;

    const double2* ag = (const double2*)(g_attn2 + (size_t)(b*SS + s0)*KK);
    for (int i = tid; i < 128*KK/2; i += 128) ((double2*)attn_s)[i] = ag[i];
    __syncthreads();

    double2 zr[KK];
    const double2* zg = (const double2*)(g_z + (size_t)b*KK*DD);
    #pragma unroll
    for (int k = 0; k < KK; ++k) zr[k] = zg[k*128 + tid];

    double2* og = (double2*)out + (size_t)(b*SS + s0)*128 + tid;
    for (int t = 0; t < 128; ++t) {
        const double2* ar = (const double2*)(attn_s + t*KK);
        double a0 = 0.0, a1 = 0.0;
        #pragma unroll
        for (int q = 0; q < 10; ++q) {
            double2 av = ar[q];                      // broadcast LDS.128
            ffma2(a0, av.x, zr[2*q].x);   ffma2(a1, av.x, zr[2*q].y);
            ffma2(a0, av.y, zr[2*q+1].x); ffma2(a1, av.y, zr[2*q+1].y);
        }
        double2 r; r.x = a0; r.y = a1;
        og[(size_t)t*128] = r;                       // STG.128
    }
}

// =====================================================================
extern "C" void kernel_launch(void* const* d_in, const int* in_sizes, int n_in,
                              void* d_out, int out_size)
{
    const float* x   = (const float*)d_in[0];
    const float* pos = (const float*)d_in[1];
    const float* lsc = (const float*)d_in[2];
    const float* amp = (const float*)d_in[3];
    const float* wv  = (const float*)d_in[4];
    const float* wo  = (const float*)d_in[5];
    float* out = (float*)d_out;

    const int sm1 = KK*128*16 + 128*9*16 + 64*4;     // 59648 B
    cudaFuncSetAttribute(k1a_attn, cudaFuncAttributeMaxDynamicSharedMemorySize, sm1);

    k0_setup<<<1, 640>>>(pos, lsc, amp);
    k1a_attn<<<dim3(64, BB), 128, sm1>>>(x, pos);
    k1b_ypart<<<dim3(64, BB), 256>>>(x);
    k2_reduce<<<(BB*KK*DD + 255)/256, 256>>>();
    k3_proj_v<<<dim3(64, BB), 256>>>(wv);
    k4_proj_o<<<dim3(64, BB), 256>>>(wo);
    k5_scatter<<<dim3(64, BB), 128>>>(out);
}

// round 4
// speedup vs baseline: 1.8821x; 1.0059x over previous
#include <cuda_runtime.h>

#define BB 4
#define SS 8192
#define DD 512
#define KK 20
#define BKD (BB*KK*DD)   // 40960

// ---- scratch (device globals: allocation-free) ----
__device__ double g_attn2[BB*SS*KK];              // dup-packed (a,a)  5.2 MB
__device__ double g_ypart[BB*64*KK*(DD/2)];       // packed pairs     10.5 MB
__device__ float  g_y4[4*BKD];                    // quarter partials
__device__ float  g_y[BKD];
__device__ float  g_tmp[BKD];
__device__ float  g_z[BKD];

// ---- f32x2 helpers ----
__device__ __forceinline__ void ffma2(double& acc, double a, double b) {
    asm("fma.rn.f32x2 %0, %1, %2, %0;" : "+d"(acc) : "d"(a), "d"(b));
}
__device__ __forceinline__ float2 dsplit(double v) {
    float2 f;
    asm("mov.b64 {%0, %1}, %2;" : "=f"(f.x), "=f"(f.y) : "d"(v));
    return f;
}
__device__ __forceinline__ double ddup(float a) {
    double d;
    asm("mov.b64 %0, {%1, %1};" : "=d"(d) : "f"(a));
    return d;
}

// =====================================================================
// k1a: RBF attention.  grid(64,B), 256 thr = (128 tokens x 2 k-halves).
// Per-CTA splat constants computed in-kernel (k0 folded in).
// =====================================================================
__global__ __launch_bounds__(256)
void k1a_attn(const float* __restrict__ x, const float* __restrict__ pos,
              const float* __restrict__ lsc, const float* __restrict__ amp)
{
    extern __shared__ char smraw[];
    double2* pos2 = (double2*)smraw;                 // [20][128]  40960 B
    float4*  xs   = (float4*)(pos2 + KK*128);        // [128][9]   18432 B
    float*   xch  = (float*)(xs + 128*9);            // [128][10]   5120 B
    float*   cst  = xch + 128*10;                    // 64 floats

    const int b   = blockIdx.y, s0 = blockIdx.x*128;
    const int tid = threadIdx.x;
    const int t   = tid & 127;          // token
    const int h   = tid >> 7;           // k-half (0: splats 0-9, 1: 10-19)
    const int kb  = h*10;

    // stage positions
    const double2* pg = (const double2*)pos;
    for (int i = tid; i < KK*128; i += 256) pos2[i] = pg[i];
    __syncthreads();

    // per-CTA constants: warp w handles splats w, w+8, w+16
    {
        int w = tid >> 5, l = tid & 31;
        for (int k = w; k < KK; k += 8) {
            const double2* pr = pos2 + k*128 + l*4;
            float s = 0.f;
            #pragma unroll
            for (int j = 0; j < 4; ++j) {
                float2 a = dsplit(pr[j].x), q = dsplit(pr[j].y);
                s += a.x*a.x + a.y*a.y + q.x*q.x + q.y*q.y;
            }
            #pragma unroll
            for (int off = 16; off; off >>= 1) s += __shfl_xor_sync(0xffffffffu, s, off);
            if (l == 0) {
                float sc = expf(lsc[k]);
                cst[k]      = -0.5f/(sc*sc);
                cst[20 + k] = amp[k];
                cst[40 + k] = s;
            }
        }
    }

    const float4* xg = (const float4*)(x + ((size_t)b*SS + s0)*DD);
    float4 pf[4];
    #pragma unroll
    for (int j = 0; j < 4; ++j) {
        int i = tid + j*256;
        pf[j] = xg[(size_t)(i>>3)*128 + (i&7)];
    }

    double acc2[10];
    #pragma unroll
    for (int k = 0; k < 10; ++k) acc2[k] = 0.0;
    double x2a = 0.0;

    for (int dc = 0; dc < 16; ++dc) {
        __syncthreads();
        #pragma unroll
        for (int j = 0; j < 4; ++j) {
            int i = tid + j*256;
            xs[(i>>3)*9 + (i&7)] = pf[j];
        }
        __syncthreads();
        if (dc < 15) {
            #pragma unroll
            for (int j = 0; j < 4; ++j) {
                int i = tid + j*256;
                pf[j] = xg[(size_t)(i>>3)*128 + (dc+1)*8 + (i&7)];
            }
        }
        const double2* xr = (const double2*)xs + t*9;
        #pragma unroll
        for (int c = 0; c < 8; ++c) {
            double2 xv = xr[c];
            ffma2(x2a, xv.x, xv.x);
            ffma2(x2a, xv.y, xv.y);
            const double2* pc = pos2 + dc*8 + c;
            #pragma unroll
            for (int kk = 0; kk < 10; ++kk) {
                double2 pv = pc[(kb + kk)*128];      // uniform broadcast LDS.128
                ffma2(acc2[kk], xv.x, pv.x);
                ffma2(acc2[kk], xv.y, pv.y);
            }
        }
    }

    // exchange upper-half dot products
    if (h == 1) {
        #pragma unroll
        for (int kk = 0; kk < 10; ++kk) {
            float2 f = dsplit(acc2[kk]);
            xch[t*10 + kk] = f.x + f.y;
        }
    }
    __syncthreads();

    if (h == 0) {
        float2 xf = dsplit(x2a);
        float x2 = xf.x + xf.y;
        float g[KK]; float gsum = 0.f;
        #pragma unroll
        for (int kk = 0; kk < 10; ++kk) {
            float2 f = dsplit(acc2[kk]);
            float xc = f.x + f.y;
            float d2 = fmaxf(x2 - 2.f*xc + cst[40+kk], 0.f);
            float gg = cst[20+kk] * expf(cst[kk]*d2);
            g[kk] = gg; gsum += gg;
        }
        #pragma unroll
        for (int kk = 10; kk < 20; ++kk) {
            float xc = xch[t*10 + (kk-10)];
            float d2 = fmaxf(x2 - 2.f*xc + cst[40+kk], 0.f);
            float gg = cst[20+kk] * expf(cst[kk]*d2);
            g[kk] = gg; gsum += gg;
        }
        float inv = 1.0f/(gsum + 1e-8f);
        double2* ag = (double2*)(g_attn2 + (size_t)(b*SS + s0 + t)*KK);
        #pragma unroll
        for (int q = 0; q < 10; ++q) {
            double2 pk; pk.x = ddup(g[2*q]*inv); pk.y = ddup(g[2*q+1]*inv);
            ag[q] = pk;
        }
    }
}

// =====================================================================
// k1b: partial y[k][d] = sum_t attn[t][k] x[t][d].
// grid(64,B), 512 thr = (256 d-pairs x 2 k-halves), 8-deep prefetch.
// =====================================================================
__global__ __launch_bounds__(512)
void k1b_ypart(const float* __restrict__ x)
{
    __shared__ double attn_s[128*KK];                // 20480 B
    const int b = blockIdx.y, ch = blockIdx.x, s0 = ch*128;
    const int tid = threadIdx.x;
    const int dp  = tid & 255;          // d-pair
    const int h   = tid >> 8;           // k-half
    const int kb  = h*10;

    const double2* ag = (const double2*)(g_attn2 + (size_t)(b*SS + s0)*KK);
    for (int i = tid; i < 128*KK/2; i += 512) ((double2*)attn_s)[i] = ag[i];
    __syncthreads();

    double acc2[10];
    #pragma unroll
    for (int k = 0; k < 10; ++k) acc2[k] = 0.0;

    const double* xcol = (const double*)x + (size_t)(b*SS + s0)*(DD/2) + dp;
    double xd[8];
    #pragma unroll
    for (int j = 0; j < 8; ++j) xd[j] = xcol[(size_t)j*(DD/2)];

    for (int tt = 0; tt < 128; tt += 8) {
        double xn[8];
        if (tt + 8 < 128) {
            #pragma unroll
            for (int j = 0; j < 8; ++j) xn[j] = xcol[(size_t)(tt+8+j)*(DD/2)];
        }
        #pragma unroll
        for (int u = 0; u < 8; ++u) {
            const double2* ar = (const double2*)(attn_s + (tt+u)*KK) + h*5;
            #pragma unroll
            for (int q = 0; q < 5; ++q) {
                double2 a2 = ar[q];                  // broadcast LDS.128
                ffma2(acc2[2*q],   a2.x, xd[u]);
                ffma2(acc2[2*q+1], a2.y, xd[u]);
            }
        }
        #pragma unroll
        for (int j = 0; j < 8; ++j) xd[j] = xn[j];
    }
    double* yp = g_ypart + (size_t)((b*64 + ch)*KK)*(DD/2) + dp;
    #pragma unroll
    for (int kk = 0; kk < 10; ++kk) yp[(kb + kk)*(DD/2)] = acc2[kk];
}

// =====================================================================
// k2: 64 chunks -> 4 quarter partials.  grid(160,4), 256 thr.
// =====================================================================
__global__ void k2_reduce()
{
    const int q   = blockIdx.y;
    const int idx = blockIdx.x*256 + threadIdx.x;    // < 40960
    const int b   = idx / (KK*DD);
    const int rem = idx - b*(KK*DD);
    const float* p = (const float*)g_ypart + (size_t)b*64*KK*DD + rem
                   + (size_t)q*16*KK*DD;
    float s = 0.f;
    #pragma unroll
    for (int c = 0; c < 16; ++c) s += p[(size_t)c*KK*DD];
    g_y4[(size_t)q*BKD + idx] = s;
}

// k2b: 4 quarters -> final y
__global__ void k2b_final()
{
    const int idx = blockIdx.x*256 + threadIdx.x;
    float a = g_y4[idx]         + g_y4[BKD + idx];
    float b = g_y4[2*BKD + idx] + g_y4[3*BKD + idx];
    g_y[idx] = a + b;
}

// =====================================================================
// Projections: warp per (e,b) row; W in regs, y LDG (L1/L2-hot), shfl.
// =====================================================================
__device__ __forceinline__
void proj_body(const float* __restrict__ in, const float* __restrict__ W,
               float* __restrict__ out)
{
    const int b = blockIdx.y;
    const int e = blockIdx.x*8 + (threadIdx.x >> 5);
    const int l = threadIdx.x & 31;

    const double2* wr = (const double2*)(W + (size_t)e*DD) + l*4;
    double2 w0 = wr[0], w1 = wr[1], w2 = wr[2], w3 = wr[3];

    const double2* yb = (const double2*)(in + (size_t)b*KK*DD) + l*4;
    float res = 0.f;
    #pragma unroll
    for (int k = 0; k < KK; ++k) {
        const double2* yr = yb + k*128;
        double2 y0 = yr[0], y1 = yr[1], y2 = yr[2], y3 = yr[3];
        double accA = 0.0, accB = 0.0;
        ffma2(accA, w0.x, y0.x); ffma2(accB, w0.y, y0.y);
        ffma2(accA, w1.x, y1.x); ffma2(accB, w1.y, y1.y);
        ffma2(accA, w2.x, y2.x); ffma2(accB, w2.y, y2.y);
        ffma2(accA, w3.x, y3.x); ffma2(accB, w3.y, y3.y);
        float2 fa = dsplit(accA), fb = dsplit(accB);
        float s = (fa.x + fa.y) + (fb.x + fb.y);
        #pragma unroll
        for (int off = 16; off; off >>= 1) s += __shfl_xor_sync(0xffffffffu, s, off);
        if (l == k) res = s;
    }
    if (l < KK) out[((size_t)b*KK + l)*DD + e] = res;
}

__global__ __launch_bounds__(256) void k3_proj_v(const float* __restrict__ W)
{ proj_body(g_y, W, g_tmp); }
__global__ __launch_bounds__(256) void k4_proj_o(const float* __restrict__ W)
{ proj_body(g_tmp, W, g_z); }

// =====================================================================
// k5: out[s][:] = sum_k attn[s][k] z[k][:].  grid(128,B), 128 thr,
// 64-token chunks.  z in regs; attn broadcast from smem.
// =====================================================================
__global__ __launch_bounds__(128)
void k5_scatter(float* __restrict__ out)
{
    __shared__ double attn_s[64*KK];                 // 10240 B
    const int b = blockIdx.y, s0 = blockIdx.x*64, tid = threadIdx.x;

    const double2* ag = (const double2*)(g_attn2 + (size_t)(b*SS + s0)*KK);
    for (int i = tid; i < 64*KK/2; i += 128) ((double2*)attn_s)[i] = ag[i];
    __syncthreads();

    double2 zr[KK];
    const double2* zg = (const double2*)(g_z + (size_t)b*KK*DD);
    #pragma unroll
    for (int k = 0; k < KK; ++k) zr[k] = zg[k*128 + tid];

    double2* og = (double2*)out + (size_t)(b*SS + s0)*128 + tid;
    for (int t = 0; t < 64; ++t) {
        const double2* ar = (const double2*)(attn_s + t*KK);
        double a0 = 0.0, a1 = 0.0;
        #pragma unroll
        for (int q = 0; q < 10; ++q) {
            double2 av = ar[q];                      // broadcast LDS.128
            ffma2(a0, av.x, zr[2*q].x);   ffma2(a1, av.x, zr[2*q].y);
            ffma2(a0, av.y, zr[2*q+1].x); ffma2(a1, av.y, zr[2*q+1].y);
        }
        double2 r; r.x = a0; r.y = a1;
        og[(size_t)t*128] = r;                       // STG.128
    }
}

// =====================================================================
extern "C" void kernel_launch(void* const* d_in, const int* in_sizes, int n_in,
                              void* d_out, int out_size)
{
    const float* x   = (const float*)d_in[0];
    const float* pos = (const float*)d_in[1];
    const float* lsc = (const float*)d_in[2];
    const float* amp = (const float*)d_in[3];
    const float* wv  = (const float*)d_in[4];
    const float* wo  = (const float*)d_in[5];
    float* out = (float*)d_out;

    const int sm1 = KK*128*16 + 128*9*16 + 128*10*4 + 64*4;  // 64768 B
    cudaFuncSetAttribute(k1a_attn, cudaFuncAttributeMaxDynamicSharedMemorySize, sm1);

    k1a_attn<<<dim3(64, BB), 256, sm1>>>(x, pos, lsc, amp);
    k1b_ypart<<<dim3(64, BB), 512>>>(x);
    k2_reduce<<<dim3(160, 4), 256>>>();
    k2b_final<<<160, 256>>>();
    k3_proj_v<<<dim3(64, BB), 256>>>(wv);
    k4_proj_o<<<dim3(64, BB), 256>>>(wo);
    k5_scatter<<<dim3(128, BB), 128>>>(out);
}

// round 5
// speedup vs baseline: 1.9111x; 1.0154x over previous
#include <cuda_runtime.h>

#define BB 4
#define SS 8192
#define DD 512
#define KK 20
#define NCTA 128
#define TPB 256
#define TOK 256
#define NCH 32
#define BKD (BB*KK*DD)   // 40960

// ---- scratch (device globals: allocation-free) ----
__device__ double   g_ypart[BB*NCH*KK*(DD/2)];   // packed f32x2 pairs, 5.2 MB
__device__ float    g_y[BKD];
__device__ float    g_tmp[BKD];
__device__ float    g_z[BKD];
__device__ unsigned g_bar_cnt = 0;
__device__ unsigned g_bar_gen = 0;

// ---- f32x2 helpers ----
__device__ __forceinline__ void ffma2(double& acc, double a, double b) {
    asm("fma.rn.f32x2 %0, %1, %2, %0;" : "+d"(acc) : "d"(a), "d"(b));
}
__device__ __forceinline__ float2 dsplit(double v) {
    float2 f;
    asm("mov.b64 {%0, %1}, %2;" : "=f"(f.x), "=f"(f.y) : "d"(v));
    return f;
}
__device__ __forceinline__ double ddup(float a) {
    double d;
    asm("mov.b64 %0, {%1, %1};" : "=d"(d) : "f"(a));
    return d;
}

// ---- grid-wide barrier (all NCTA CTAs co-resident; sense-reversing) ----
__device__ __forceinline__ void grid_bar(unsigned& gen)
{
    __syncthreads();
    if (threadIdx.x == 0) {
        unsigned target = gen + 1;
        __threadfence();
        unsigned prev = atomicAdd(&g_bar_cnt, 1u);
        if (prev == NCTA - 1) {
            atomicExch(&g_bar_cnt, 0u);
            __threadfence();
            atomicExch(&g_bar_gen, target);
        } else {
            while (atomicAdd(&g_bar_gen, 0u) != target) { }
        }
        __threadfence();
        gen = target;
    }
    __syncthreads();
}

// ---- projection stage: warp per (b,e) row, 2 rows/warp ----
__device__ __forceinline__
void proj_stage(const float* __restrict__ in, const float* __restrict__ W,
                float* __restrict__ out, int cta, int tid)
{
    const int l = tid & 31;
    int wg = cta*8 + (tid >> 5);
    #pragma unroll
    for (int rep = 0; rep < 2; ++rep, wg += 1024) {
        const int bb = wg >> 9, e = wg & 511;
        const double2* wr = (const double2*)(W + (size_t)e*DD) + l*4;
        double2 w0 = wr[0], w1 = wr[1], w2 = wr[2], w3 = wr[3];
        const double2* yb = (const double2*)(in + (size_t)bb*KK*DD) + l*4;
        float res = 0.f;
        #pragma unroll
        for (int k = 0; k < KK; ++k) {
            const double2* yr = yb + k*128;
            double2 y0 = yr[0], y1 = yr[1], y2 = yr[2], y3 = yr[3];
            double accA = 0.0, accB = 0.0;
            ffma2(accA, w0.x, y0.x); ffma2(accB, w0.y, y0.y);
            ffma2(accA, w1.x, y1.x); ffma2(accB, w1.y, y1.y);
            ffma2(accA, w2.x, y2.x); ffma2(accB, w2.y, y2.y);
            ffma2(accA, w3.x, y3.x); ffma2(accB, w3.y, y3.y);
            float2 fa = dsplit(accA), fb = dsplit(accB);
            float s = (fa.x + fa.y) + (fb.x + fb.y);
            #pragma unroll
            for (int off = 16; off; off >>= 1) s += __shfl_xor_sync(0xffffffffu, s, off);
            if (l == k) res = s;
        }
        if (l < KK) out[((size_t)bb*KK + l)*DD + e] = res;
    }
}

// =====================================================================
// Mega-kernel: all 5 stages, 128 CTAs x 256 threads, 4 grid barriers.
// CTA j owns chunk (b = j>>5, ch = j&31): 256 tokens in stages 1 and 5;
// the chunk's attn stays resident in SMEM the whole time.
// =====================================================================
__global__ __launch_bounds__(TPB)
void mega(const float* __restrict__ x, const float* __restrict__ pos,
          const float* __restrict__ lsc, const float* __restrict__ amp,
          const float* __restrict__ wv, const float* __restrict__ wo,
          float* __restrict__ out)
{
    extern __shared__ char smraw[];
    double2* pos2   = (double2*)smraw;                  // [20][128]   40960 B
    float4*  xs     = (float4*)(pos2 + KK*128);         // [256][9]    36864 B
    double*  attn_s = (double*)(xs + TOK*9);            // [256][20]   40960 B
    float*   cst    = (float*)(attn_s + TOK*KK);        // 64 floats

    const int cta = blockIdx.x;
    const int tid = threadIdx.x;
    const int b   = cta >> 5;
    const int ch  = cta & 31;
    const int s0  = ch * TOK;

    unsigned gen = 0;
    if (tid == 0) gen = atomicAdd(&g_bar_gen, 0u);      // entry generation

    // ---------------- stage 1a: positions + splat constants ----------------
    const double2* pg = (const double2*)pos;
    for (int i = tid; i < KK*128; i += TPB) pos2[i] = pg[i];
    __syncthreads();
    {
        int w = tid >> 5, l = tid & 31;
        for (int k = w; k < KK; k += 8) {
            const double2* pr = pos2 + k*128 + l*4;
            float s = 0.f;
            #pragma unroll
            for (int j = 0; j < 4; ++j) {
                float2 a = dsplit(pr[j].x), q = dsplit(pr[j].y);
                s += a.x*a.x + a.y*a.y + q.x*q.x + q.y*q.y;
            }
            #pragma unroll
            for (int off = 16; off; off >>= 1) s += __shfl_xor_sync(0xffffffffu, s, off);
            if (l == 0) {
                float sc = expf(lsc[k]);
                cst[k]      = -0.5f/(sc*sc);
                cst[20 + k] = amp[k];
                cst[40 + k] = s;
            }
        }
    }

    // ---------------- stage 1b: phase A (xc dots), thread = token ----------
    const float4* xg = (const float4*)(x + ((size_t)b*SS + s0)*DD);
    float4 pf[8];
    #pragma unroll
    for (int j = 0; j < 8; ++j) {
        int i = tid + j*TPB;
        pf[j] = xg[(size_t)(i>>3)*128 + (i&7)];
    }

    double acc2[KK];
    #pragma unroll
    for (int k = 0; k < KK; ++k) acc2[k] = 0.0;
    double x2a = 0.0;

    for (int dc = 0; dc < 16; ++dc) {
        __syncthreads();
        #pragma unroll
        for (int j = 0; j < 8; ++j) {
            int i = tid + j*TPB;
            xs[(i>>3)*9 + (i&7)] = pf[j];
        }
        __syncthreads();
        if (dc < 15) {
            #pragma unroll
            for (int j = 0; j < 8; ++j) {
                int i = tid + j*TPB;
                pf[j] = xg[(size_t)(i>>3)*128 + (dc+1)*8 + (i&7)];
            }
        }
        const double2* xr = (const double2*)xs + tid*9;
        #pragma unroll
        for (int c = 0; c < 8; ++c) {
            double2 xv = xr[c];
            ffma2(x2a, xv.x, xv.x);
            ffma2(x2a, xv.y, xv.y);
            const double2* pc = pos2 + dc*8 + c;
            #pragma unroll
            for (int k = 0; k < KK; ++k) {
                double2 pv = pc[k*128];              // uniform broadcast LDS.128
                ffma2(acc2[k], xv.x, pv.x);
                ffma2(acc2[k], xv.y, pv.y);
            }
        }
    }

    // ---------------- stage 1c: gauss -> attn (dup-packed, SMEM only) ------
    {
        float2 xf = dsplit(x2a);
        float x2 = xf.x + xf.y;
        float g[KK]; float gsum = 0.f;
        #pragma unroll
        for (int k = 0; k < KK; ++k) {
            float2 f = dsplit(acc2[k]);
            float xc = f.x + f.y;
            float d2 = fmaxf(x2 - 2.f*xc + cst[40+k], 0.f);
            float gg = cst[20+k] * expf(cst[k]*d2);
            g[k] = gg; gsum += gg;
        }
        float inv = 1.0f/(gsum + 1e-8f);
        double2* as = (double2*)(attn_s + tid*KK);
        #pragma unroll
        for (int q = 0; q < 10; ++q) {
            double2 pk; pk.x = ddup(g[2*q]*inv); pk.y = ddup(g[2*q+1]*inv);
            as[q] = pk;
        }
    }
    __syncthreads();

    // ---------------- stage 1d: ypart = attn^T @ x, thread = d-pair --------
    {
        double acc[KK];
        #pragma unroll
        for (int k = 0; k < KK; ++k) acc[k] = 0.0;

        const double* xcol = (const double*)x + (size_t)(b*SS + s0)*(DD/2) + tid;
        double xd[8];
        #pragma unroll
        for (int j = 0; j < 8; ++j) xd[j] = xcol[(size_t)j*(DD/2)];

        for (int t = 0; t < TOK; t += 8) {
            double xn[8];
            if (t + 8 < TOK) {
                #pragma unroll
                for (int j = 0; j < 8; ++j) xn[j] = xcol[(size_t)(t+8+j)*(DD/2)];
            }
            #pragma unroll
            for (int u = 0; u < 8; ++u) {
                const double2* ar = (const double2*)(attn_s + (t+u)*KK);
                #pragma unroll
                for (int q = 0; q < 10; ++q) {
                    double2 a2 = ar[q];              // broadcast LDS.128
                    ffma2(acc[2*q],   a2.x, xd[u]);
                    ffma2(acc[2*q+1], a2.y, xd[u]);
                }
            }
            #pragma unroll
            for (int j = 0; j < 8; ++j) xd[j] = xn[j];
        }
        double* yp = g_ypart + (size_t)cta*KK*(DD/2) + tid;
        #pragma unroll
        for (int k = 0; k < KK; ++k) yp[k*(DD/2)] = acc[k];
    }
    grid_bar(gen);

    // ---------------- stage 2: reduce 32 chunks -> y ------------------------
    for (int idx = cta*TPB + tid; idx < BKD; idx += NCTA*TPB) {
        int bb = idx / (KK*DD);
        int rem = idx - bb*(KK*DD);
        const float* p = (const float*)g_ypart + (size_t)bb*NCH*KK*DD + rem;
        float s = 0.f;
        #pragma unroll
        for (int c = 0; c < NCH; ++c) s += p[(size_t)c*KK*DD];
        g_y[idx] = s;
    }
    grid_bar(gen);

    // ---------------- stage 3: z1 = y @ wv^T --------------------------------
    proj_stage(g_y, wv, g_tmp, cta, tid);
    grid_bar(gen);

    // ---------------- stage 4: z = z1 @ wo^T --------------------------------
    proj_stage(g_tmp, wo, g_z, cta, tid);
    grid_bar(gen);

    // ---------------- stage 5: out = attn @ z (attn still in SMEM) ---------
    {
        const int col = tid & 127;                   // double2 column (4 floats)
        const int th  = tid >> 7;                    // token half
        double2 zr[KK];
        const double2* zg = (const double2*)g_z + (size_t)b*KK*128;
        #pragma unroll
        for (int k = 0; k < KK; ++k) zr[k] = zg[k*128 + col];

        const int t0 = th*128;
        double2* og = (double2*)out + (size_t)(b*SS + s0 + t0)*128 + col;
        for (int t = 0; t < 128; ++t) {
            const double2* ar = (const double2*)(attn_s + (t0 + t)*KK);
            double a0 = 0.0, a1 = 0.0;
            #pragma unroll
            for (int q = 0; q < 10; ++q) {
                double2 av = ar[q];                  // broadcast LDS.128
                ffma2(a0, av.x, zr[2*q].x);   ffma2(a1, av.x, zr[2*q].y);
                ffma2(a0, av.y, zr[2*q+1].x); ffma2(a1, av.y, zr[2*q+1].y);
            }
            double2 r; r.x = a0; r.y = a1;
            og[(size_t)t*128] = r;                   // STG.128
        }
    }
}

// =====================================================================
extern "C" void kernel_launch(void* const* d_in, const int* in_sizes, int n_in,
                              void* d_out, int out_size)
{
    const float* x   = (const float*)d_in[0];
    const float* pos = (const float*)d_in[1];
    const float* lsc = (const float*)d_in[2];
    const float* amp = (const float*)d_in[3];
    const float* wv  = (const float*)d_in[4];
    const float* wo  = (const float*)d_in[5];
    float* out = (float*)d_out;

    const int smb = KK*128*16 + TOK*9*16 + TOK*KK*8 + 64*4;   // 119040 B
    cudaFuncSetAttribute(mega, cudaFuncAttributeMaxDynamicSharedMemorySize, smb);

    mega<<<NCTA, TPB, smb>>>(x, pos, lsc, amp, wv, wo, out);
}

// round 6
// speedup vs baseline: 2.1703x; 1.1356x over previous
#include <cuda_runtime.h>

#define BB 4
#define SS 8192
#define DD 512
#define KK 20
#define NCTA 128
#define TPB 512
#define TOK 256
#define NCH 32
#define BKD (BB*KK*DD)   // 40960

// ---- scratch (device globals: allocation-free) ----
__device__ double   g_ypart[BB*NCH*KK*(DD/2)];   // packed f32x2 pairs, 5.2 MB
__device__ float    g_y[BKD];
__device__ float    g_tmp[BKD];
__device__ float    g_z[BKD];
__device__ unsigned g_bar_cnt = 0;
__device__ unsigned g_bar_gen = 0;

// ---- f32x2 helpers ----
__device__ __forceinline__ void ffma2(double& acc, double a, double b) {
    asm("fma.rn.f32x2 %0, %1, %2, %0;" : "+d"(acc) : "d"(a), "d"(b));
}
__device__ __forceinline__ float2 dsplit(double v) {
    float2 f;
    asm("mov.b64 {%0, %1}, %2;" : "=f"(f.x), "=f"(f.y) : "d"(v));
    return f;
}
__device__ __forceinline__ double ddup(float a) {
    double d;
    asm("mov.b64 %0, {%1, %1};" : "=d"(d) : "f"(a));
    return d;
}

// ---- grid-wide barrier (all NCTA CTAs co-resident; sense-reversing) ----
__device__ __forceinline__ void grid_bar(unsigned& gen)
{
    __syncthreads();
    if (threadIdx.x == 0) {
        unsigned target = gen + 1;
        __threadfence();
        unsigned prev = atomicAdd(&g_bar_cnt, 1u);
        if (prev == NCTA - 1) {
            atomicExch(&g_bar_cnt, 0u);
            __threadfence();
            atomicExch(&g_bar_gen, target);
        } else {
            while (atomicAdd(&g_bar_gen, 0u) != target) { }
        }
        __threadfence();
        gen = target;
    }
    __syncthreads();
}

// =====================================================================
// Mega-kernel: all 5 stages, 128 CTAs x 512 threads (16 warps/SM).
// CTA j owns chunk (b = j>>5, ch = j&31) of 256 tokens; the chunk's
// attn lives in SMEM from stage 1 through stage 5.
// =====================================================================
__global__ __launch_bounds__(TPB)
void mega(const float* __restrict__ x, const float* __restrict__ pos,
          const float* __restrict__ lsc, const float* __restrict__ amp,
          const float* __restrict__ wv, const float* __restrict__ wo,
          float* __restrict__ out)
{
    extern __shared__ char smraw[];
    double2* pos2   = (double2*)smraw;                  // [20][128]   40960 B
    float4*  xs     = (float4*)(pos2 + KK*128);         // [256][9]    36864 B
    double*  attn_s = (double*)(xs + TOK*9);            // [256][20]   40960 B
    float*   cst    = (float*)(attn_s + TOK*KK);        // 64 floats
    float*   xch    = (float*)xs;                       // alias (xs dead by then)

    const int cta = blockIdx.x;
    const int tid = threadIdx.x;
    const int b   = cta >> 5;
    const int s0  = (cta & 31) * TOK;
    const int t   = tid & 255;          // token (stages 1b/1c)
    const int h   = tid >> 8;           // k-half (0: splats 0-9, 1: 10-19)
    const int kb  = h*10;

    unsigned gen = 0;
    if (tid == 0) gen = atomicAdd(&g_bar_gen, 0u);      // entry generation

    // ---------------- stage 1a: positions + splat constants ----------------
    const double2* pg = (const double2*)pos;
    for (int i = tid; i < KK*128; i += TPB) pos2[i] = pg[i];
    __syncthreads();
    {
        int w = tid >> 5, l = tid & 31;
        for (int k = w; k < KK; k += 16) {
            const double2* pr = pos2 + k*128 + l*4;
            float s = 0.f;
            #pragma unroll
            for (int j = 0; j < 4; ++j) {
                float2 a = dsplit(pr[j].x), q = dsplit(pr[j].y);
                s += a.x*a.x + a.y*a.y + q.x*q.x + q.y*q.y;
            }
            #pragma unroll
            for (int off = 16; off; off >>= 1) s += __shfl_xor_sync(0xffffffffu, s, off);
            if (l == 0) {
                float sc = expf(lsc[k]);
                cst[k]      = -0.5f/(sc*sc);
                cst[20 + k] = amp[k];
                cst[40 + k] = s;
            }
        }
    }

    // ---------------- stage 1b: xc dots, thread = (token, k-half) ----------
    const float4* xg = (const float4*)(x + ((size_t)b*SS + s0)*DD);
    float4 pf[4];
    #pragma unroll
    for (int j = 0; j < 4; ++j) {
        int i = tid + j*TPB;
        pf[j] = xg[(size_t)(i>>3)*128 + (i&7)];
    }

    double acc2[10];
    #pragma unroll
    for (int k = 0; k < 10; ++k) acc2[k] = 0.0;
    double x2a = 0.0;

    for (int dc = 0; dc < 16; ++dc) {
        __syncthreads();
        #pragma unroll
        for (int j = 0; j < 4; ++j) {
            int i = tid + j*TPB;
            xs[(i>>3)*9 + (i&7)] = pf[j];
        }
        __syncthreads();
        if (dc < 15) {
            #pragma unroll
            for (int j = 0; j < 4; ++j) {
                int i = tid + j*TPB;
                pf[j] = xg[(size_t)(i>>3)*128 + (dc+1)*8 + (i&7)];
            }
        }
        const double2* xr = (const double2*)xs + t*9;
        #pragma unroll
        for (int c = 0; c < 8; ++c) {
            double2 xv = xr[c];
            ffma2(x2a, xv.x, xv.x);
            ffma2(x2a, xv.y, xv.y);
            const double2* pc = pos2 + dc*8 + c;
            #pragma unroll
            for (int kk = 0; kk < 10; ++kk) {
                double2 pv = pc[(kb + kk)*128];      // warp-uniform broadcast
                ffma2(acc2[kk], xv.x, pv.x);
                ffma2(acc2[kk], xv.y, pv.y);
            }
        }
    }
    __syncthreads();                                  // xs reads done

    // ---------------- stage 1c: exchange + gauss -> attn (SMEM) ------------
    if (h == 1) {
        #pragma unroll
        for (int kk = 0; kk < 10; ++kk) {
            float2 f = dsplit(acc2[kk]);
            xch[t*10 + kk] = f.x + f.y;
        }
    }
    __syncthreads();
    if (h == 0) {
        float2 xf = dsplit(x2a);
        float x2 = xf.x + xf.y;
        float g[KK]; float gsum = 0.f;
        #pragma unroll
        for (int kk = 0; kk < 10; ++kk) {
            float2 f = dsplit(acc2[kk]);
            float xc = f.x + f.y;
            float d2 = fmaxf(x2 - 2.f*xc + cst[40+kk], 0.f);
            float gg = cst[20+kk] * expf(cst[kk]*d2);
            g[kk] = gg; gsum += gg;
        }
        #pragma unroll
        for (int kk = 10; kk < 20; ++kk) {
            float xc = xch[t*10 + (kk-10)];
            float d2 = fmaxf(x2 - 2.f*xc + cst[40+kk], 0.f);
            float gg = cst[20+kk] * expf(cst[kk]*d2);
            g[kk] = gg; gsum += gg;
        }
        float inv = 1.0f/(gsum + 1e-8f);
        double2* as = (double2*)(attn_s + t*KK);
        #pragma unroll
        for (int q = 0; q < 10; ++q) {
            double2 pk; pk.x = ddup(g[2*q]*inv); pk.y = ddup(g[2*q+1]*inv);
            as[q] = pk;
        }
    }
    __syncthreads();

    // ---------------- stage 1d: ypart = attn^T @ x, thread = (d-pair, half)
    {
        double acc[10];
        #pragma unroll
        for (int k = 0; k < 10; ++k) acc[k] = 0.0;

        const double* xcol = (const double*)x + (size_t)(b*SS + s0)*(DD/2) + t;
        double xd[8];
        #pragma unroll
        for (int j = 0; j < 8; ++j) xd[j] = xcol[(size_t)j*(DD/2)];

        for (int tt = 0; tt < TOK; tt += 8) {
            double xn[8];
            if (tt + 8 < TOK) {
                #pragma unroll
                for (int j = 0; j < 8; ++j) xn[j] = xcol[(size_t)(tt+8+j)*(DD/2)];
            }
            #pragma unroll
            for (int u = 0; u < 8; ++u) {
                const double2* ar = (const double2*)(attn_s + (tt+u)*KK) + h*5;
                #pragma unroll
                for (int q = 0; q < 5; ++q) {
                    double2 a2 = ar[q];              // warp-uniform broadcast
                    ffma2(acc[2*q],   a2.x, xd[u]);
                    ffma2(acc[2*q+1], a2.y, xd[u]);
                }
            }
            #pragma unroll
            for (int j = 0; j < 8; ++j) xd[j] = xn[j];
        }
        double* yp = g_ypart + (size_t)cta*KK*(DD/2) + t;
        #pragma unroll
        for (int kk = 0; kk < 10; ++kk) yp[(kb + kk)*(DD/2)] = acc[kk];
    }
    grid_bar(gen);

    // ---------------- stage 2: reduce 32 chunks -> y ------------------------
    {
        int idx = cta*TPB + tid;
        if (idx < BKD) {
            int bb = idx / (KK*DD);
            int rem = idx - bb*(KK*DD);
            const float* p = (const float*)g_ypart + (size_t)bb*NCH*KK*DD + rem;
            float s = 0.f;
            #pragma unroll
            for (int c = 0; c < NCH; ++c) s += p[(size_t)c*KK*DD];
            g_y[idx] = s;
        }
    }
    grid_bar(gen);

    // ---------------- stages 3+4: projections (warp per (b,e) row) ---------
    #pragma unroll
    for (int stage = 0; stage < 2; ++stage) {
        const float* in = stage ? g_tmp : g_y;
        const float* W  = stage ? wo    : wv;
        float*      o   = stage ? g_z   : g_tmp;
        const int l = tid & 31;
        const int wg = cta*16 + (tid >> 5);          // 2048 warps = 4b x 512e
        const int bb = wg >> 9, e = wg & 511;
        const double2* wr = (const double2*)(W + (size_t)e*DD) + l*4;
        double2 w0 = wr[0], w1 = wr[1], w2 = wr[2], w3 = wr[3];
        const double2* yb = (const double2*)(in + (size_t)bb*KK*DD) + l*4;
        float res = 0.f;
        #pragma unroll
        for (int k = 0; k < KK; ++k) {
            const double2* yr = yb + k*128;
            double2 y0 = yr[0], y1 = yr[1], y2 = yr[2], y3 = yr[3];
            double accA = 0.0, accB = 0.0;
            ffma2(accA, w0.x, y0.x); ffma2(accB, w0.y, y0.y);
            ffma2(accA, w1.x, y1.x); ffma2(accB, w1.y, y1.y);
            ffma2(accA, w2.x, y2.x); ffma2(accB, w2.y, y2.y);
            ffma2(accA, w3.x, y3.x); ffma2(accB, w3.y, y3.y);
            float2 fa = dsplit(accA), fb = dsplit(accB);
            float s = (fa.x + fa.y) + (fb.x + fb.y);
            #pragma unroll
            for (int off = 16; off; off >>= 1) s += __shfl_xor_sync(0xffffffffu, s, off);
            if (l == k) res = s;
        }
        if (l < KK) o[((size_t)bb*KK + l)*DD + e] = res;
        grid_bar(gen);
    }

    // ---------------- stage 5: out = attn @ z (attn still in SMEM) ---------
    {
        const int col = tid & 127;                   // double2 column (4 floats)
        const int t0  = (tid >> 7) * 64;             // token quarter
        double2 zr[KK];
        const double2* zg = (const double2*)g_z + (size_t)b*KK*128;
        #pragma unroll
        for (int k = 0; k < KK; ++k) zr[k] = zg[k*128 + col];

        double2* og = (double2*)out + (size_t)(b*SS + s0 + t0)*128 + col;
        for (int tt = 0; tt < 64; ++tt) {
            const double2* ar = (const double2*)(attn_s + (t0 + tt)*KK);
            double a0 = 0.0, a1 = 0.0;
            #pragma unroll
            for (int q = 0; q < 10; ++q) {
                double2 av = ar[q];                  // warp-uniform broadcast
                ffma2(a0, av.x, zr[2*q].x);   ffma2(a1, av.x, zr[2*q].y);
                ffma2(a0, av.y, zr[2*q+1].x); ffma2(a1, av.y, zr[2*q+1].y);
            }
            double2 r; r.x = a0; r.y = a1;
            og[(size_t)tt*128] = r;                  // STG.128
        }
    }
}

// =====================================================================
extern "C" void kernel_launch(void* const* d_in, const int* in_sizes, int n_in,
                              void* d_out, int out_size)
{
    const float* x   = (const float*)d_in[0];
    const float* pos = (const float*)d_in[1];
    const float* lsc = (const float*)d_in[2];
    const float* amp = (const float*)d_in[3];
    const float* wv  = (const float*)d_in[4];
    const float* wo  = (const float*)d_in[5];
    float* out = (float*)d_out;

    const int smb = KK*128*16 + TOK*9*16 + TOK*KK*8 + 64*4;   // 119040 B
    cudaFuncSetAttribute(mega, cudaFuncAttributeMaxDynamicSharedMemorySize, smb);

    mega<<<NCTA, TPB, smb>>>(x, pos, lsc, amp, wv, wo, out);
}